// round 6
// baseline (speedup 1.0000x reference)
#include <cuda_runtime.h>

// Problem constants (fixed shapes from reference):
//   x:          [16,64,64,256] fp32  -> N_ROWS=65536 rows of D_DIM=256
//   dictionary: [256,1024]     fp32  -> D_DIM x K_CODES
// Output: q_st (16777216 fp32) followed by loss (1 fp32).
//
// CORRECTNESS-CRITICAL: the reference (XLA CPU fp32) computes
//   t2(k) = fl( fl(nf + c_k) - fl(2 * sim_k) ),  argmin_k first-index,
// where nf/c_k are sequential fp32 square-sums over d=0..255 and sim is an
// Eigen fp32 FMA chain over d=0..255. Distances sit near 256, so they are
// quantized at ulp(256)=3.05e-5; reproducing the argmin requires replicating
// this arithmetic (order + association + roundings) exactly. Do NOT change
// the accumulation order or fuse/unfuse these ops.
#define D_DIM   256
#define K_CODES 1024
#define N_ROWS  65536

#define MTILE   128
#define NTILE   128
#define KCHUNK  32
#define ASTRIDE 260     // padded row stride for x tile (260 % 32 == 4 -> conflict-free LDS)
#define THREADS 256

// Scratch (no cudaMalloc allowed): transposed dictionary + code norms + loss accum
__device__ float  g_dictT[K_CODES * D_DIM];
__device__ float  g_c[K_CODES];
__device__ double g_loss;

// ---------------------------------------------------------------------------
// Kernel 1: transpose dictionary (for coalesced gather) and compute
// c_k = sum_d fl(d*d) with SEQUENTIAL fp32 adds in d order (mul then add,
// matching an XLA elementwise-square + ordered reduce). Zero loss accum.
// ---------------------------------------------------------------------------
__global__ void vq_prep(const float* __restrict__ dict) {
    int k = blockIdx.x * blockDim.x + threadIdx.x;
    if (k == 0) g_loss = 0.0;
    if (k < K_CODES) {
        float c = 0.f;
        for (int d = 0; d < D_DIM; ++d) {
            float v = dict[(size_t)d * K_CODES + k];   // coalesced across lanes
            g_dictT[k * D_DIM + d] = v;
            c = __fadd_rn(c, __fmul_rn(v, v));         // no FMA contraction
        }
        g_c[k] = c;
    }
}

// ---------------------------------------------------------------------------
// Kernel 2: per 128-row tile: sim = f.d_k as a sequential fp32 FMA chain over
// d=0..255 (bitwise-matching Eigen's contraction), then replicate the
// reference's fp32 distance rounding:
//   t1 = fl(nf_r + c_k); t2 = fl(t1 - fl(2*sim)); argmin first-index.
// Then gather q = 0.5*dictT[k*] (exact), write output, accumulate loss.
// Thread map: j = t&15 owns 8 codes, i = t>>4 owns rows {i, i+16, ..., i+112}.
// ---------------------------------------------------------------------------
__global__ __launch_bounds__(THREADS, 1)
void vq_main(const float* __restrict__ x,
             const float* __restrict__ dict,
             float* __restrict__ out) {
    extern __shared__ float smem[];
    float* sA   = smem;                              // MTILE*ASTRIDE fp32 (x tile)
    float* sB   = sA + MTILE * ASTRIDE;              // KCHUNK*NTILE fp32 (dict chunk)
    float* sBv  = sB + KCHUNK * NTILE;               // MTILE*16 best values
    int*   sBi  = (int*)(sBv + MTILE * 16);          // MTILE*16 best indices
    int*   sIdx = sBi + MTILE * 16;                  // MTILE final indices
    float* sNf  = (float*)(sIdx + MTILE);            // MTILE row norms ||f||^2

    const int t = threadIdx.x;
    const int j = t & 15;
    const int i = t >> 4;
    const size_t row0 = (size_t)blockIdx.x * MTILE;

    // Load x tile (float4, coalesced) into padded SMEM
    {
        const float4* xv = (const float4*)(x + row0 * D_DIM);
        for (int e = t; e < MTILE * (D_DIM / 4); e += THREADS) {
            int r  = e >> 6;          // D_DIM/4 == 64
            int c4 = e & 63;
            float4 v = xv[r * 64 + c4];
            float* dst = sA + r * ASTRIDE + c4 * 4;
            dst[0] = v.x; dst[1] = v.y; dst[2] = v.z; dst[3] = v.w;
        }
    }
    __syncthreads();

    // Per-row nf = sum_d fl(x*x), sequential fp32 adds in d order.
    if (t < MTILE) {
        float s = 0.f;
        const float* rowp = sA + t * ASTRIDE;
        for (int d = 0; d < D_DIM; ++d)
            s = __fadd_rn(s, __fmul_rn(rowp[d], rowp[d]));
        sNf[t] = s;
    }
    __syncthreads();

    float nf_m[8];
    #pragma unroll
    for (int m = 0; m < 8; ++m) nf_m[m] = sNf[i + 16 * m];

    float bv[8];
    int   bi[8];
    #pragma unroll
    for (int m = 0; m < 8; ++m) { bv[m] = __int_as_float(0x7f800000); bi[m] = 0; }

    for (int tt = 0; tt < K_CODES / NTILE; ++tt) {
        float acc[8][8];
        #pragma unroll
        for (int m = 0; m < 8; ++m)
            #pragma unroll
            for (int n = 0; n < 8; ++n) acc[m][n] = 0.f;

        for (int kt = 0; kt < D_DIM / KCHUNK; ++kt) {
            __syncthreads();   // protect sB from previous iteration readers
            // Load dict chunk: rows d = kt*32..+31, codes tt*128..+127 (coalesced)
            {
                const int base_d = kt * KCHUNK;
                const int base_c = tt * NTILE;
                for (int e = t; e < KCHUNK * (NTILE / 4); e += THREADS) {
                    int r  = e >> 5;      // NTILE/4 == 32
                    int c4 = e & 31;
                    float4 v = *(const float4*)(dict + (size_t)(base_d + r) * K_CODES
                                                + base_c + c4 * 4);
                    *(float4*)(sB + r * NTILE + c4 * 4) = v;
                }
            }
            __syncthreads();

            // Sequential FMA chain in ascending d = kt*32+kk: ORDER IS LOAD-BEARING.
            #pragma unroll 8
            for (int kk = 0; kk < KCHUNK; ++kk) {
                float a[8];
                #pragma unroll
                for (int m = 0; m < 8; ++m)
                    a[m] = sA[(i + 16 * m) * ASTRIDE + kt * KCHUNK + kk];
                float4 b0 = *(const float4*)(sB + kk * NTILE + j * 8);
                float4 b1 = *(const float4*)(sB + kk * NTILE + j * 8 + 4);
                float b[8] = {b0.x, b0.y, b0.z, b0.w, b1.x, b1.y, b1.z, b1.w};
                #pragma unroll
                for (int m = 0; m < 8; ++m)
                    #pragma unroll
                    for (int n = 0; n < 8; ++n)
                        acc[m][n] = fmaf(a[m], b[n], acc[m][n]);
            }
        }

        // Replicate reference rounding: t1 = fl(nf + c_k); t2 = fl(t1 - fl(2*s)).
        // Ascending n + strict '<' keeps the FIRST minimal index (jnp.argmin).
        const int cbase = tt * NTILE + j * 8;
        #pragma unroll
        for (int n = 0; n < 8; ++n) {
            float ck = g_c[cbase + n];
            int   code = cbase + n;
            #pragma unroll
            for (int m = 0; m < 8; ++m) {
                float t1 = __fadd_rn(nf_m[m], ck);
                float v  = __fsub_rn(t1, __fmul_rn(2.f, acc[m][n]));
                if (v < bv[m]) { bv[m] = v; bi[m] = code; }
            }
        }
    }

    __syncthreads();
    #pragma unroll
    for (int m = 0; m < 8; ++m) {
        int r = i + 16 * m;
        sBv[r * 16 + j] = bv[m];
        sBi[r * 16 + j] = bi[m];
    }
    __syncthreads();

    if (t < MTILE) {
        float best = sBv[t * 16];
        int   bidx = sBi[t * 16];
        #pragma unroll
        for (int jj = 1; jj < 16; ++jj) {
            float v = sBv[t * 16 + jj];
            int  idx = sBi[t * 16 + jj];
            if (v < best || (v == best && idx < bidx)) { best = v; bidx = idx; }
        }
        sIdx[t] = bidx;
    }
    __syncthreads();

    // Epilogue: gather q = 0.5*dictT[idx][d] (exact halving; coalesced reads),
    // write output, accumulate loss partial.
    float lsum = 0.f;
    for (int e = t; e < MTILE * D_DIM; e += THREADS) {
        int r = e >> 8;           // D_DIM == 256
        int d = e & 255;
        int idx = sIdx[r];
        float q  = 0.5f * g_dictT[idx * D_DIM + d];
        float xv = sA[r * ASTRIDE + d];
        float df = xv - q;
        lsum = fmaf(df, df, lsum);
        out[(row0 + r) * D_DIM + d] = q;
    }

    // Block reduce lsum -> double atomic
    #pragma unroll
    for (int o = 16; o > 0; o >>= 1)
        lsum += __shfl_xor_sync(0xffffffffu, lsum, o);
    __syncthreads();                       // done reading sBv; safe to reuse
    if ((t & 31) == 0) sBv[t >> 5] = lsum;
    __syncthreads();
    if (t == 0) {
        float s = 0.f;
        #pragma unroll
        for (int w = 0; w < THREADS / 32; ++w) s += sBv[w];
        atomicAdd(&g_loss, (double)s);
    }
}

// ---------------------------------------------------------------------------
// Kernel 3: loss = 1.25 * mean((x - q)^2)   (dict_loss + 0.25*commitment,
// both numerically identical since stop_gradient is identity in value)
// ---------------------------------------------------------------------------
__global__ void vq_finalize(float* __restrict__ out, int loss_idx) {
    out[loss_idx] = (float)(1.25 * g_loss * (1.0 / (double)(N_ROWS * D_DIM)));
}

static const int SMEM_BYTES =
    (MTILE * ASTRIDE + KCHUNK * NTILE + MTILE * 16) * (int)sizeof(float)
    + MTILE * 16 * (int)sizeof(int) + MTILE * (int)sizeof(int)
    + MTILE * (int)sizeof(float);

extern "C" void kernel_launch(void* const* d_in, const int* in_sizes, int n_in,
                              void* d_out, int out_size) {
    const float* x    = (const float*)d_in[0];
    const float* dict = (const float*)d_in[1];
    float* out = (float*)d_out;

    cudaFuncSetAttribute(vq_main, cudaFuncAttributeMaxDynamicSharedMemorySize,
                         SMEM_BYTES);

    vq_prep<<<(K_CODES + 255) / 256, 256>>>(dict);
    vq_main<<<N_ROWS / MTILE, THREADS, SMEM_BYTES>>>(x, dict, out);
    vq_finalize<<<1, 1>>>(out, out_size - 1);
}